// round 1
// baseline (speedup 1.0000x reference)
#include <cuda_runtime.h>
#include <math.h>

#define N_ROWS 16384
#define DIM    512
#define BM     128
#define BN     128
#define BK     16
#define NSPLIT 2
#define COLS_PER_SPLIT (N_ROWS / NSPLIT)   // 8192
#define CTILES (COLS_PER_SPLIT / BN)       // 64
#define KCHUNKS (DIM / BK)                 // 32

// Scratch (allocation-free rule: __device__ globals)
__device__ unsigned long long g_best[NSPLIT][N_ROWS];
__device__ float g_logrho[N_ROWS];

// ---- packed (value, index) key: larger key == larger value, tie -> smaller idx ----
__device__ __forceinline__ unsigned long long pack_key(float v, int idx) {
    unsigned u = __float_as_uint(v);
    u = (u & 0x80000000u) ? ~u : (u | 0x80000000u);   // order-preserving flip
    return ((unsigned long long)u << 32) | (unsigned)(~(unsigned)idx);
}

// f32x2 packed-pair FMA helpers (sm_103a dual-rate fp32 path)
#define FMA2(d, a, b) asm("fma.rn.f32x2 %0, %1, %2, %0;" : "+l"(d) : "l"(a), "l"(b))
#define PACK2(d, f)   asm("mov.b64 %0, {%1, %1};"       : "=l"(d) : "f"(f))
#define UNPACK2(lo, hi, s) asm("mov.b64 {%0, %1}, %2;" : "=f"(lo), "=f"(hi) : "l"(s))

__global__ __launch_bounds__(256, 2)
void nn_argmax_kernel(const float* __restrict__ x) {
    __shared__ float As[BK][BM];
    __shared__ float Bs[BK][BN];

    const int tid = threadIdx.x;
    const int tx  = tid & 15;        // 0..15 -> column groups
    const int ty  = tid >> 4;        // 0..15 -> row groups (8 rows each)
    const int rowBase  = blockIdx.x * BM;
    const int split    = blockIdx.y;
    const int colBase0 = split * COLS_PER_SPLIT;

    // global->smem mapping: thread loads float4 q=tid (rows 0..63) and q=tid+256 (rows 64..127)
    const int qrow0 = tid >> 2;      // 0..63
    const int qc4   = tid & 3;       // which float4 within the 16-wide k chunk

    const float* baseA = x + (size_t)rowBase * DIM;

    float rv[8]; int ri[8];
    #pragma unroll
    for (int r = 0; r < 8; r++) { rv[r] = -INFINITY; ri[r] = 0; }

    for (int ct = 0; ct < CTILES; ct++) {
        const int colBase = colBase0 + ct * BN;
        const float* baseB = x + (size_t)colBase * DIM;

        unsigned long long acc[8][4];
        #pragma unroll
        for (int r = 0; r < 8; r++)
            #pragma unroll
            for (int p = 0; p < 4; p++) acc[r][p] = 0ULL;

        float4 pa0, pa1, pb0, pb1;
        // prefetch k-chunk 0
        {
            const float* pa = baseA + qrow0 * DIM + qc4 * 4;
            pa0 = *(const float4*)pa;
            pa1 = *(const float4*)(pa + 64 * DIM);
            const float* pb = baseB + qrow0 * DIM + qc4 * 4;
            pb0 = *(const float4*)pb;
            pb1 = *(const float4*)(pb + 64 * DIM);
        }

        for (int kc = 0; kc < KCHUNKS; kc++) {
            // stage (transposed) into smem
            {
                const int kk = qc4 * 4;
                As[kk+0][qrow0] = pa0.x; As[kk+1][qrow0] = pa0.y;
                As[kk+2][qrow0] = pa0.z; As[kk+3][qrow0] = pa0.w;
                As[kk+0][qrow0+64] = pa1.x; As[kk+1][qrow0+64] = pa1.y;
                As[kk+2][qrow0+64] = pa1.z; As[kk+3][qrow0+64] = pa1.w;
                Bs[kk+0][qrow0] = pb0.x; Bs[kk+1][qrow0] = pb0.y;
                Bs[kk+2][qrow0] = pb0.z; Bs[kk+3][qrow0] = pb0.w;
                Bs[kk+0][qrow0+64] = pb1.x; Bs[kk+1][qrow0+64] = pb1.y;
                Bs[kk+2][qrow0+64] = pb1.z; Bs[kk+3][qrow0+64] = pb1.w;
            }
            __syncthreads();

            // register prefetch of next k-chunk overlaps with compute
            if (kc + 1 < KCHUNKS) {
                const int k0 = (kc + 1) * BK;
                const float* pa = baseA + qrow0 * DIM + k0 + qc4 * 4;
                pa0 = *(const float4*)pa;
                pa1 = *(const float4*)(pa + 64 * DIM);
                const float* pb = baseB + qrow0 * DIM + k0 + qc4 * 4;
                pb0 = *(const float4*)pb;
                pb1 = *(const float4*)(pb + 64 * DIM);
            }

            #pragma unroll
            for (int k = 0; k < BK; k++) {
                const float4 a0 = *(const float4*)&As[k][ty * 8];
                const float4 a1 = *(const float4*)&As[k][ty * 8 + 4];
                const ulonglong2 b0 = *(const ulonglong2*)&Bs[k][tx * 4];
                const ulonglong2 b1 = *(const ulonglong2*)&Bs[k][tx * 4 + 64];

                unsigned long long aa;
#define DOROW(r, av)                                    \
                PACK2(aa, av);                           \
                FMA2(acc[r][0], aa, b0.x);               \
                FMA2(acc[r][1], aa, b0.y);               \
                FMA2(acc[r][2], aa, b1.x);               \
                FMA2(acc[r][3], aa, b1.y);
                DOROW(0, a0.x) DOROW(1, a0.y) DOROW(2, a0.z) DOROW(3, a0.w)
                DOROW(4, a1.x) DOROW(5, a1.y) DOROW(6, a1.z) DOROW(7, a1.w)
#undef DOROW
            }
            __syncthreads();
        }

        // epilogue: per-row masked argmax over this 128-column tile
        #pragma unroll
        for (int r = 0; r < 8; r++) {
            const int gr = rowBase + ty * 8 + r;
            float bv = -INFINITY; int bi = 0;
            #pragma unroll
            for (int p = 0; p < 4; p++) {
                const int gc0 = colBase + ((p < 2) ? (tx * 4 + p * 2)
                                                   : (64 + tx * 4 + (p - 2) * 2));
                float lo, hi;
                UNPACK2(lo, hi, acc[r][p]);
                if (gc0     != gr && lo > bv) { bv = lo; bi = gc0;     }
                if (gc0 + 1 != gr && hi > bv) { bv = hi; bi = gc0 + 1; }
            }
            // reduce across the 16 threads sharing these rows (tie -> smaller index)
            #pragma unroll
            for (int off = 8; off > 0; off >>= 1) {
                const float ov = __shfl_down_sync(0xffffffffu, bv, off, 16);
                const int   oi = __shfl_down_sync(0xffffffffu, bi, off, 16);
                if (ov > bv || (ov == bv && oi < bi)) { bv = ov; bi = oi; }
            }
            if (tx == 0) {
                if (bv > rv[r] || (bv == rv[r] && bi < ri[r])) { rv[r] = bv; ri[r] = bi; }
            }
        }
    }

    if (tx == 0) {
        #pragma unroll
        for (int r = 0; r < 8; r++)
            g_best[split][rowBase + ty * 8 + r] = pack_key(rv[r], ri[r]);
    }
}

// rho_i = || x_i - x_{nn(i)} + 1e-6 ||_2 ;  g_logrho[i] = log(rho_i + 1e-8)
__global__ void rho_kernel(const float* __restrict__ x) {
    const int row = blockIdx.x;
    const int t   = threadIdx.x;       // 128 threads
    const unsigned long long p0 = g_best[0][row];
    const unsigned long long p1 = g_best[1][row];
    const unsigned long long p  = (p0 > p1) ? p0 : p1;
    const int nn = (int)(~(unsigned)(p & 0xffffffffULL));

    const float4 a = *(const float4*)(x + (size_t)row * DIM + t * 4);
    const float4 b = *(const float4*)(x + (size_t)nn  * DIM + t * 4);
    const float d0 = a.x - b.x + 1e-6f;
    const float d1 = a.y - b.y + 1e-6f;
    const float d2 = a.z - b.z + 1e-6f;
    const float d3 = a.w - b.w + 1e-6f;
    float s = d0*d0 + d1*d1 + d2*d2 + d3*d3;

    #pragma unroll
    for (int off = 16; off > 0; off >>= 1)
        s += __shfl_down_sync(0xffffffffu, s, off);

    __shared__ float ws[4];
    if ((t & 31) == 0) ws[t >> 5] = s;
    __syncthreads();
    if (t == 0) {
        const float tot = ws[0] + ws[1] + ws[2] + ws[3];
        g_logrho[row] = logf(sqrtf(tot) + 1e-8f);
    }
}

// loss = -mean(g_logrho)   (deterministic fixed-order sum in double)
__global__ void final_kernel(float* __restrict__ out) {
    __shared__ double sh[256];
    double s = 0.0;
    for (int i = threadIdx.x; i < N_ROWS; i += 256) s += (double)g_logrho[i];
    sh[threadIdx.x] = s;
    __syncthreads();
    for (int off = 128; off > 0; off >>= 1) {
        if (threadIdx.x < off) sh[threadIdx.x] += sh[threadIdx.x + off];
        __syncthreads();
    }
    if (threadIdx.x == 0) out[0] = (float)(-sh[0] / (double)N_ROWS);
}

extern "C" void kernel_launch(void* const* d_in, const int* in_sizes, int n_in,
                              void* d_out, int out_size) {
    const float* x = (const float*)d_in[0];
    dim3 grid(N_ROWS / BM, NSPLIT);
    nn_argmax_kernel<<<grid, 256>>>(x);
    rho_kernel<<<N_ROWS, 128>>>(x);
    final_kernel<<<1, 256>>>((float*)d_out);
}

// round 7
// speedup vs baseline: 7.6455x; 7.6455x over previous
#include <cuda_runtime.h>
#include <cuda_bf16.h>
#include <math.h>
#include <stdint.h>

#define N_ROWS 16384
#define DIM    512
#define BM     128
#define BN     128
#define BK     32
#define NSTAGE 4
#define KITERS (DIM / BK)          // 16

// padded smem row: 32 halves -> 40 halves (80 bytes) for conflict-free ldmatrix
#define ROWB   80
#define STAGE_BYTES (BM * ROWB)    // 10240
#define SM_A(s) ((s) * STAGE_BYTES)
#define SM_B(s) (NSTAGE * STAGE_BYTES + (s) * STAGE_BYTES)
#define SM_TOTAL (2 * NSTAGE * STAGE_BYTES)   // 81920

// ---------------- scratch (allocation-free rule) ----------------
__device__ __align__(16) __nv_bfloat16 g_xbf[N_ROWS * DIM];   // 16 MB
__device__ unsigned long long g_best[N_ROWS];
__device__ float g_logrho[N_ROWS];

// ---------------- helpers ----------------
__device__ __forceinline__ uint32_t smem_u32(const void* p) {
    uint32_t a;
    asm("{ .reg .u64 t; cvta.to.shared.u64 t, %1; cvt.u32.u64 %0, t; }" : "=r"(a) : "l"(p));
    return a;
}

__device__ __forceinline__ unsigned long long pack_key(float v, int col) {
    unsigned u = __float_as_uint(v);
    u = (u & 0x80000000u) ? ~u : (u | 0x80000000u);   // order-preserving flip
    return ((unsigned long long)u << 32) | (unsigned)(~(unsigned)col); // tie -> smaller col
}

#define CP_ASYNC(sm, gm) asm volatile("cp.async.cg.shared.global [%0], [%1], 16;" :: "r"(sm), "l"(gm))
#define CP_COMMIT()      asm volatile("cp.async.commit_group;" ::: "memory")
#define CP_WAIT(n)       asm volatile("cp.async.wait_group %0;" :: "n"(n) : "memory")

#define LDSM4(r0, r1, r2, r3, addr)                                             \
    asm volatile("ldmatrix.sync.aligned.m8n8.x4.shared.b16 {%0,%1,%2,%3}, [%4];" \
                 : "=r"(r0), "=r"(r1), "=r"(r2), "=r"(r3) : "r"(addr))

#define MMA(c0, c1, c2, c3, a0, a1, a2, a3, b0, b1)                              \
    asm volatile("mma.sync.aligned.m16n8k16.row.col.f32.bf16.bf16.f32 "          \
                 "{%0,%1,%2,%3}, {%4,%5,%6,%7}, {%8,%9}, {%0,%1,%2,%3};"         \
                 : "+f"(c0), "+f"(c1), "+f"(c2), "+f"(c3)                        \
                 : "r"(a0), "r"(a1), "r"(a2), "r"(a3), "r"(b0), "r"(b1))

// ---------------- prep: fp32 -> bf16 (+ init g_best) ----------------
__global__ void prep_kernel(const float* __restrict__ x) {
    const int gid = blockIdx.x * blockDim.x + threadIdx.x;
    const int i = gid * 4;
    float4 v = *(const float4*)(x + i);
    __nv_bfloat162 a, b;
    a.x = __float2bfloat16(v.x); a.y = __float2bfloat16(v.y);
    b.x = __float2bfloat16(v.z); b.y = __float2bfloat16(v.w);
    *(__nv_bfloat162*)(g_xbf + i)     = a;
    *(__nv_bfloat162*)(g_xbf + i + 2) = b;
    if (gid < N_ROWS) g_best[gid] = 0ULL;
}

// ---------------- fused bf16 GEMM (mma.sync) + row argmax ----------------
__global__ __launch_bounds__(256, 2)
void nn_gemm_kernel() {
    extern __shared__ char smem[];
    const uint32_t sb = smem_u32(smem);

    const int tid  = threadIdx.x;
    const int lane = tid & 31;
    const int wid  = tid >> 5;
    const int warp_m = wid & 3;          // 4 row groups of 32
    const int warp_n = wid >> 2;         // 2 col groups of 64
    const int cb = blockIdx.x;           // column tile
    const int rb = blockIdx.y;           // row tile

    const __nv_bfloat16* Ag = g_xbf + (size_t)rb * BM * DIM;
    const __nv_bfloat16* Bg = g_xbf + (size_t)cb * BN * DIM;

    // per-thread global-load assignment: chunks tid and tid+256 (row = id/4, c4 = id%4)
    const int r0 = tid >> 2, c0 = tid & 3;

    float acc[2][8][4];
    #pragma unroll
    for (int mi = 0; mi < 2; mi++)
        #pragma unroll
        for (int ni = 0; ni < 8; ni++)
            #pragma unroll
            for (int j = 0; j < 4; j++) acc[mi][ni][j] = 0.f;

    // ldmatrix per-lane addressing
    const int lrow = (lane & 7) + ((lane >> 3) & 1) * 8;
    const int lkof = ((lane >> 4) & 1) * 8;

    // prologue: issue stages 0..2
    #pragma unroll
    for (int s = 0; s < NSTAGE - 1; s++) {
        const int k0 = s * BK;
        CP_ASYNC(sb + SM_A(s) + r0 * ROWB + c0 * 16,        Ag + r0 * DIM + k0 + c0 * 8);
        CP_ASYNC(sb + SM_A(s) + (r0 + 64) * ROWB + c0 * 16, Ag + (r0 + 64) * DIM + k0 + c0 * 8);
        CP_ASYNC(sb + SM_B(s) + r0 * ROWB + c0 * 16,        Bg + r0 * DIM + k0 + c0 * 8);
        CP_ASYNC(sb + SM_B(s) + (r0 + 64) * ROWB + c0 * 16, Bg + (r0 + 64) * DIM + k0 + c0 * 8);
        CP_COMMIT();
    }

    for (int kb = 0; kb < KITERS; kb++) {
        CP_WAIT(2);
        __syncthreads();

        // issue stage kb+3
        if (kb + NSTAGE - 1 < KITERS) {
            const int s = (kb + NSTAGE - 1) & (NSTAGE - 1);
            const int k0 = (kb + NSTAGE - 1) * BK;
            CP_ASYNC(sb + SM_A(s) + r0 * ROWB + c0 * 16,        Ag + r0 * DIM + k0 + c0 * 8);
            CP_ASYNC(sb + SM_A(s) + (r0 + 64) * ROWB + c0 * 16, Ag + (r0 + 64) * DIM + k0 + c0 * 8);
            CP_ASYNC(sb + SM_B(s) + r0 * ROWB + c0 * 16,        Bg + r0 * DIM + k0 + c0 * 8);
            CP_ASYNC(sb + SM_B(s) + (r0 + 64) * ROWB + c0 * 16, Bg + (r0 + 64) * DIM + k0 + c0 * 8);
        }
        CP_COMMIT();

        const int st = kb & (NSTAGE - 1);
        const uint32_t a_base = sb + SM_A(st) + (warp_m * 32 + lrow) * ROWB;
        const uint32_t b_base = sb + SM_B(st) + (warp_n * 64 + lrow) * ROWB;

        #pragma unroll
        for (int kk = 0; kk < BK; kk += 16) {
            const uint32_t koff = (kk + lkof) * 2;
            uint32_t a0[4], a1[4], b[4][4];
            LDSM4(a0[0], a0[1], a0[2], a0[3], a_base + koff);
            LDSM4(a1[0], a1[1], a1[2], a1[3], a_base + 16 * ROWB + koff);
            #pragma unroll
            for (int nb = 0; nb < 4; nb++)
                LDSM4(b[nb][0], b[nb][1], b[nb][2], b[nb][3], b_base + nb * 16 * ROWB + koff);

            // ldmatrix x4 register order: m0=n0-7/k0-7, m1=n8-15/k0-7,
            //                             m2=n0-7/k8-15, m3=n8-15/k8-15
            // mma B operand {b0,b1} = {k0-7, k8-15} of ONE n8 block:
            //   first n8 block  -> (reg0, reg2)
            //   second n8 block -> (reg1, reg3)
            #pragma unroll
            for (int nb = 0; nb < 4; nb++) {
                MMA(acc[0][nb*2][0],   acc[0][nb*2][1],   acc[0][nb*2][2],   acc[0][nb*2][3],
                    a0[0], a0[1], a0[2], a0[3], b[nb][0], b[nb][2]);
                MMA(acc[0][nb*2+1][0], acc[0][nb*2+1][1], acc[0][nb*2+1][2], acc[0][nb*2+1][3],
                    a0[0], a0[1], a0[2], a0[3], b[nb][1], b[nb][3]);
                MMA(acc[1][nb*2][0],   acc[1][nb*2][1],   acc[1][nb*2][2],   acc[1][nb*2][3],
                    a1[0], a1[1], a1[2], a1[3], b[nb][0], b[nb][2]);
                MMA(acc[1][nb*2+1][0], acc[1][nb*2+1][1], acc[1][nb*2+1][2], acc[1][nb*2+1][3],
                    a1[0], a1[1], a1[2], a1[3], b[nb][1], b[nb][3]);
            }
        }
        __syncthreads();
    }

    // ---- epilogue: per-row argmax (diagonal masked), key = (value, ~col) ----
    const int grp = lane >> 2;
    const int qc  = lane & 3;
    #pragma unroll
    for (int mi = 0; mi < 2; mi++) {
        #pragma unroll
        for (int rsel = 0; rsel < 2; rsel++) {
            const int grow = rb * BM + warp_m * 32 + mi * 16 + rsel * 8 + grp;
            unsigned long long key = 0ULL;
            #pragma unroll
            for (int ni = 0; ni < 8; ni++) {
                #pragma unroll
                for (int j = 0; j < 2; j++) {
                    const int gcol = cb * BN + warp_n * 64 + ni * 8 + qc * 2 + j;
                    if (gcol != grow) {
                        const unsigned long long k2 = pack_key(acc[mi][ni][rsel * 2 + j], gcol);
                        if (k2 > key) key = k2;
                    }
                }
            }
            // reduce over the 4 lanes of this group (qc = 0..3)
            #pragma unroll
            for (int off = 1; off < 4; off <<= 1) {
                const unsigned long long ok =
                    ((unsigned long long)__shfl_xor_sync(0xffffffffu, (unsigned)(key >> 32), off) << 32) |
                    (unsigned)__shfl_xor_sync(0xffffffffu, (unsigned)key, off);
                if (ok > key) key = ok;
            }
            if (qc == 0) atomicMax(&g_best[grow], key);
        }
    }
}

// ---------------- rho: exact fp32 from original x ----------------
__global__ void rho_kernel(const float* __restrict__ x) {
    const int row = blockIdx.x;
    const int t   = threadIdx.x;   // 128
    const unsigned long long key = g_best[row];
    const int nn = (int)(~(unsigned)(key & 0xffffffffULL));

    const float4 a = *(const float4*)(x + (size_t)row * DIM + t * 4);
    const float4 b = *(const float4*)(x + (size_t)nn  * DIM + t * 4);
    const float d0 = a.x - b.x + 1e-6f;
    const float d1 = a.y - b.y + 1e-6f;
    const float d2 = a.z - b.z + 1e-6f;
    const float d3 = a.w - b.w + 1e-6f;
    float s = d0 * d0 + d1 * d1 + d2 * d2 + d3 * d3;

    #pragma unroll
    for (int off = 16; off > 0; off >>= 1)
        s += __shfl_down_sync(0xffffffffu, s, off);

    __shared__ float ws[4];
    if ((t & 31) == 0) ws[t >> 5] = s;
    __syncthreads();
    if (t == 0) {
        const float tot = ws[0] + ws[1] + ws[2] + ws[3];
        g_logrho[row] = logf(sqrtf(tot) + 1e-8f);
    }
}

__global__ void final_kernel(float* __restrict__ out) {
    __shared__ double sh[256];
    double s = 0.0;
    for (int i = threadIdx.x; i < N_ROWS; i += 256) s += (double)g_logrho[i];
    sh[threadIdx.x] = s;
    __syncthreads();
    for (int off = 128; off > 0; off >>= 1) {
        if (threadIdx.x < off) sh[threadIdx.x] += sh[threadIdx.x + off];
        __syncthreads();
    }
    if (threadIdx.x == 0) out[0] = (float)(-sh[0] / (double)N_ROWS);
}

extern "C" void kernel_launch(void* const* d_in, const int* in_sizes, int n_in,
                              void* d_out, int out_size) {
    const float* x = (const float*)d_in[0];

    cudaFuncSetAttribute(nn_gemm_kernel, cudaFuncAttributeMaxDynamicSharedMemorySize, SM_TOTAL);

    prep_kernel<<<(N_ROWS * DIM) / (256 * 4), 256>>>(x);
    dim3 grid(N_ROWS / BN, N_ROWS / BM);
    nn_gemm_kernel<<<grid, 256, SM_TOTAL>>>();
    rho_kernel<<<N_ROWS, 128>>>(x);
    final_kernel<<<1, 256>>>((float*)d_out);
}

// round 9
// speedup vs baseline: 12.9217x; 1.6901x over previous
#include <cuda_runtime.h>
#include <cuda_bf16.h>
#include <math.h>
#include <stdint.h>

#define N_ROWS 16384
#define DIM    512
#define BM     128
#define BN     128
#define BK     32
#define NSTAGE 4
#define KITERS (DIM / BK)          // 16

// padded smem row: 32 halves -> 40 halves (80 bytes) for conflict-free ldmatrix
#define ROWB   80
#define STAGE_BYTES (BM * ROWB)    // 10240
#define SM_A(s) ((s) * STAGE_BYTES)
#define SM_B(s) (NSTAGE * STAGE_BYTES + (s) * STAGE_BYTES)
#define SM_TOTAL (2 * NSTAGE * STAGE_BYTES)   // 81920

// ---------------- scratch (allocation-free rule) ----------------
__device__ __align__(16) __nv_bfloat16 g_xbf[N_ROWS * DIM];   // 16 MB
__device__ unsigned long long g_best[N_ROWS];
__device__ float g_logrho[N_ROWS];

// ---------------- helpers ----------------
__device__ __forceinline__ uint32_t smem_u32(const void* p) {
    uint32_t a;
    asm("{ .reg .u64 t; cvta.to.shared.u64 t, %1; cvt.u32.u64 %0, t; }" : "=r"(a) : "l"(p));
    return a;
}

__device__ __forceinline__ unsigned long long pack_key(float v, int idx) {
    unsigned u = __float_as_uint(v);
    u = (u & 0x80000000u) ? ~u : (u | 0x80000000u);   // order-preserving flip
    return ((unsigned long long)u << 32) | (unsigned)(~(unsigned)idx); // tie -> smaller idx
}

__device__ __forceinline__ unsigned long long shfl_xor_u64(unsigned long long k, int off) {
    return ((unsigned long long)__shfl_xor_sync(0xffffffffu, (unsigned)(k >> 32), off) << 32) |
           (unsigned)__shfl_xor_sync(0xffffffffu, (unsigned)k, off);
}

#define CP_ASYNC(sm, gm) asm volatile("cp.async.cg.shared.global [%0], [%1], 16;" :: "r"(sm), "l"(gm))
#define CP_COMMIT()      asm volatile("cp.async.commit_group;" ::: "memory")
#define CP_WAIT(n)       asm volatile("cp.async.wait_group %0;" :: "n"(n) : "memory")

#define LDSM4(r0, r1, r2, r3, addr)                                             \
    asm volatile("ldmatrix.sync.aligned.m8n8.x4.shared.b16 {%0,%1,%2,%3}, [%4];" \
                 : "=r"(r0), "=r"(r1), "=r"(r2), "=r"(r3) : "r"(addr))

#define MMA(c0, c1, c2, c3, a0, a1, a2, a3, b0, b1)                              \
    asm volatile("mma.sync.aligned.m16n8k16.row.col.f32.bf16.bf16.f32 "          \
                 "{%0,%1,%2,%3}, {%4,%5,%6,%7}, {%8,%9}, {%0,%1,%2,%3};"         \
                 : "+f"(c0), "+f"(c1), "+f"(c2), "+f"(c3)                        \
                 : "r"(a0), "r"(a1), "r"(a2), "r"(a3), "r"(b0), "r"(b1))

// ---------------- prep: fp32 -> bf16 (+ init g_best) ----------------
__global__ void prep_kernel(const float* __restrict__ x) {
    const int gid = blockIdx.x * blockDim.x + threadIdx.x;
    const int i = gid * 4;
    float4 v = *(const float4*)(x + i);
    __nv_bfloat162 a, b;
    a.x = __float2bfloat16(v.x); a.y = __float2bfloat16(v.y);
    b.x = __float2bfloat16(v.z); b.y = __float2bfloat16(v.w);
    *(__nv_bfloat162*)(g_xbf + i)     = a;
    *(__nv_bfloat162*)(g_xbf + i + 2) = b;
    if (gid < N_ROWS) g_best[gid] = 0ULL;
}

// ---------------- fused bf16 GEMM (mma.sync) + symmetric argmax scatter ------
// Only tiles with cb >= rb are computed. Off-diagonal tiles update BOTH the
// rb-block rows (row-scan) and the cb-block rows (column-scan, by symmetry).
__global__ __launch_bounds__(256, 2)
void nn_gemm_kernel() {
    const int cb = blockIdx.x;           // column tile
    const int rb = blockIdx.y;           // row tile
    if (cb < rb) return;                 // symmetry: skip lower triangle

    extern __shared__ char smem[];
    const uint32_t sb = smem_u32(smem);

    const int tid  = threadIdx.x;
    const int lane = tid & 31;
    const int wid  = tid >> 5;
    const int warp_m = wid & 3;          // 4 row groups of 32
    const int warp_n = wid >> 2;         // 2 col groups of 64

    const __nv_bfloat16* Ag = g_xbf + (size_t)rb * BM * DIM;
    const __nv_bfloat16* Bg = g_xbf + (size_t)cb * BN * DIM;

    const int r0 = tid >> 2, c0 = tid & 3;

    float acc[2][8][4];
    #pragma unroll
    for (int mi = 0; mi < 2; mi++)
        #pragma unroll
        for (int ni = 0; ni < 8; ni++)
            #pragma unroll
            for (int j = 0; j < 4; j++) acc[mi][ni][j] = 0.f;

    const int lrow = (lane & 7) + ((lane >> 3) & 1) * 8;
    const int lkof = ((lane >> 4) & 1) * 8;

    #pragma unroll
    for (int s = 0; s < NSTAGE - 1; s++) {
        const int k0 = s * BK;
        CP_ASYNC(sb + SM_A(s) + r0 * ROWB + c0 * 16,        Ag + r0 * DIM + k0 + c0 * 8);
        CP_ASYNC(sb + SM_A(s) + (r0 + 64) * ROWB + c0 * 16, Ag + (r0 + 64) * DIM + k0 + c0 * 8);
        CP_ASYNC(sb + SM_B(s) + r0 * ROWB + c0 * 16,        Bg + r0 * DIM + k0 + c0 * 8);
        CP_ASYNC(sb + SM_B(s) + (r0 + 64) * ROWB + c0 * 16, Bg + (r0 + 64) * DIM + k0 + c0 * 8);
        CP_COMMIT();
    }

    for (int kb = 0; kb < KITERS; kb++) {
        CP_WAIT(2);
        __syncthreads();

        if (kb + NSTAGE - 1 < KITERS) {
            const int s = (kb + NSTAGE - 1) & (NSTAGE - 1);
            const int k0 = (kb + NSTAGE - 1) * BK;
            CP_ASYNC(sb + SM_A(s) + r0 * ROWB + c0 * 16,        Ag + r0 * DIM + k0 + c0 * 8);
            CP_ASYNC(sb + SM_A(s) + (r0 + 64) * ROWB + c0 * 16, Ag + (r0 + 64) * DIM + k0 + c0 * 8);
            CP_ASYNC(sb + SM_B(s) + r0 * ROWB + c0 * 16,        Bg + r0 * DIM + k0 + c0 * 8);
            CP_ASYNC(sb + SM_B(s) + (r0 + 64) * ROWB + c0 * 16, Bg + (r0 + 64) * DIM + k0 + c0 * 8);
        }
        CP_COMMIT();

        const int st = kb & (NSTAGE - 1);
        const uint32_t a_base = sb + SM_A(st) + (warp_m * 32 + lrow) * ROWB;
        const uint32_t b_base = sb + SM_B(st) + (warp_n * 64 + lrow) * ROWB;

        #pragma unroll
        for (int kk = 0; kk < BK; kk += 16) {
            const uint32_t koff = (kk + lkof) * 2;
            uint32_t a0[4], a1[4], b[4][4];
            LDSM4(a0[0], a0[1], a0[2], a0[3], a_base + koff);
            LDSM4(a1[0], a1[1], a1[2], a1[3], a_base + 16 * ROWB + koff);
            #pragma unroll
            for (int nb = 0; nb < 4; nb++)
                LDSM4(b[nb][0], b[nb][1], b[nb][2], b[nb][3], b_base + nb * 16 * ROWB + koff);

            // ldmatrix x4 order: m0=n0-7/k0-7, m1=n8-15/k0-7, m2=n0-7/k8-15, m3=n8-15/k8-15
            // mma B operand = {k0-7, k8-15} of one n8 block: (reg0,reg2) / (reg1,reg3)
            #pragma unroll
            for (int nb = 0; nb < 4; nb++) {
                MMA(acc[0][nb*2][0],   acc[0][nb*2][1],   acc[0][nb*2][2],   acc[0][nb*2][3],
                    a0[0], a0[1], a0[2], a0[3], b[nb][0], b[nb][2]);
                MMA(acc[0][nb*2+1][0], acc[0][nb*2+1][1], acc[0][nb*2+1][2], acc[0][nb*2+1][3],
                    a0[0], a0[1], a0[2], a0[3], b[nb][1], b[nb][3]);
                MMA(acc[1][nb*2][0],   acc[1][nb*2][1],   acc[1][nb*2][2],   acc[1][nb*2][3],
                    a1[0], a1[1], a1[2], a1[3], b[nb][0], b[nb][2]);
                MMA(acc[1][nb*2+1][0], acc[1][nb*2+1][1], acc[1][nb*2+1][2], acc[1][nb*2+1][3],
                    a1[0], a1[1], a1[2], a1[3], b[nb][1], b[nb][3]);
            }
        }
        __syncthreads();
    }

    const int grp = lane >> 2;
    const int qc  = lane & 3;
    const bool diag = (rb == cb);

    // ---- row-scan: update rows of the rb block ----
    #pragma unroll
    for (int mi = 0; mi < 2; mi++) {
        #pragma unroll
        for (int rsel = 0; rsel < 2; rsel++) {
            const int grow = rb * BM + warp_m * 32 + mi * 16 + rsel * 8 + grp;
            unsigned long long key = 0ULL;
            #pragma unroll
            for (int ni = 0; ni < 8; ni++) {
                #pragma unroll
                for (int j = 0; j < 2; j++) {
                    const int gcol = cb * BN + warp_n * 64 + ni * 8 + qc * 2 + j;
                    if (!diag || gcol != grow) {
                        const unsigned long long k2 = pack_key(acc[mi][ni][rsel * 2 + j], gcol);
                        if (k2 > key) key = k2;
                    }
                }
            }
            #pragma unroll
            for (int off = 1; off < 4; off <<= 1) {
                const unsigned long long ok = shfl_xor_u64(key, off);
                if (ok > key) key = ok;
            }
            if (qc == 0) atomicMax(&g_best[grow], key);
        }
    }

    // ---- column-scan (symmetry): update rows of the cb block ----
    if (!diag) {
        #pragma unroll
        for (int ni = 0; ni < 8; ni++) {
            #pragma unroll
            for (int jj = 0; jj < 2; jj++) {
                unsigned long long key = 0ULL;
                #pragma unroll
                for (int mi = 0; mi < 2; mi++) {
                    #pragma unroll
                    for (int rsel = 0; rsel < 2; rsel++) {
                        const int grow = rb * BM + warp_m * 32 + mi * 16 + rsel * 8 + grp;
                        const unsigned long long k2 = pack_key(acc[mi][ni][rsel * 2 + jj], grow);
                        if (k2 > key) key = k2;
                    }
                }
                // reduce over grp (lanes differing in bits 2..4)
                #pragma unroll
                for (int off = 4; off < 32; off <<= 1) {
                    const unsigned long long ok = shfl_xor_u64(key, off);
                    if (ok > key) key = ok;
                }
                if (grp == 0) {
                    const int gcol = cb * BN + warp_n * 64 + ni * 8 + qc * 2 + jj;
                    atomicMax(&g_best[gcol], key);
                }
            }
        }
    }
}

// ---------------- rho: exact fp32 from original x ----------------
__global__ void rho_kernel(const float* __restrict__ x) {
    const int row = blockIdx.x;
    const int t   = threadIdx.x;   // 128
    const unsigned long long key = g_best[row];
    const int nn = (int)(~(unsigned)(key & 0xffffffffULL));

    const float4 a = *(const float4*)(x + (size_t)row * DIM + t * 4);
    const float4 b = *(const float4*)(x + (size_t)nn  * DIM + t * 4);
    const float d0 = a.x - b.x + 1e-6f;
    const float d1 = a.y - b.y + 1e-6f;
    const float d2 = a.z - b.z + 1e-6f;
    const float d3 = a.w - b.w + 1e-6f;
    float s = d0 * d0 + d1 * d1 + d2 * d2 + d3 * d3;

    #pragma unroll
    for (int off = 16; off > 0; off >>= 1)
        s += __shfl_down_sync(0xffffffffu, s, off);

    __shared__ float ws[4];
    if ((t & 31) == 0) ws[t >> 5] = s;
    __syncthreads();
    if (t == 0) {
        const float tot = ws[0] + ws[1] + ws[2] + ws[3];
        g_logrho[row] = logf(sqrtf(tot) + 1e-8f);
    }
}

// loss = -mean(g_logrho): float4 loads + 4 independent double accumulators
__global__ void final_kernel(float* __restrict__ out) {
    __shared__ double sh[256];
    double s0 = 0.0, s1 = 0.0, s2 = 0.0, s3 = 0.0;
    for (int i = threadIdx.x; i < N_ROWS / 4; i += 256) {
        const float4 v = *(const float4*)(g_logrho + i * 4);
        s0 += (double)v.x; s1 += (double)v.y; s2 += (double)v.z; s3 += (double)v.w;
    }
    sh[threadIdx.x] = (s0 + s1) + (s2 + s3);
    __syncthreads();
    for (int off = 128; off > 0; off >>= 1) {
        if (threadIdx.x < off) sh[threadIdx.x] += sh[threadIdx.x + off];
        __syncthreads();
    }
    if (threadIdx.x == 0) out[0] = (float)(-sh[0] / (double)N_ROWS);
}

extern "C" void kernel_launch(void* const* d_in, const int* in_sizes, int n_in,
                              void* d_out, int out_size) {
    const float* x = (const float*)d_in[0];

    cudaFuncSetAttribute(nn_gemm_kernel, cudaFuncAttributeMaxDynamicSharedMemorySize, SM_TOTAL);

    prep_kernel<<<(N_ROWS * DIM) / (256 * 4), 256>>>(x);
    dim3 grid(N_ROWS / BN, N_ROWS / BM);
    nn_gemm_kernel<<<grid, 256, SM_TOTAL>>>();
    rho_kernel<<<N_ROWS, 128>>>(x);
    final_kernel<<<1, 256>>>((float*)d_out);
}